// round 3
// baseline (speedup 1.0000x reference)
#include <cuda_runtime.h>

// Problem constants
#define BB   32
#define CC   16
#define RES  128
#define NANG 64

// Scratch: weighted image, batch-innermost, x-neighbor-paired.
// P[(y*128 + x)*32 + b] = ( W[b][y][x], x<127 ? W[b][y][x+1] : 0 )
// where W[b][y][x] = sum_c conv_w[c] * x[b][c][y][x].
__device__ float2 g_P[RES * RES * BB];

// ---------------------------------------------------------------------------
// Kernel 1: channel-weighted image -> paired layout.
// thread t: x = t&127 (lane-contiguous, coalesced reads), y = (t>>7)&127, b = t>>14
// ---------------------------------------------------------------------------
__global__ __launch_bounds__(256) void k_weight(const float* __restrict__ x,
                                                const float* __restrict__ w) {
    int t  = blockIdx.x * 256 + threadIdx.x;       // 0 .. 524287
    int xi = t & 127;
    int y  = (t >> 7) & 127;
    int b  = t >> 14;

    const float* px = x + ((size_t)(b * CC) * RES + y) * RES + xi;
    float s = 0.f;
#pragma unroll
    for (int c = 0; c < CC; c++)
        s = fmaf(__ldg(&w[c]), __ldg(&px[(size_t)c * RES * RES]), s);

    float* Pf = (float*)g_P;
    int base = (y * 128 + xi) * 32 + b;            // float2 index
    Pf[base * 2] = s;                              // .x of (y, xi)
    if (xi > 0)    Pf[(base - 32) * 2 + 1] = s;    // .y of (y, xi-1)
    if (xi == 127) Pf[base * 2 + 1] = 0.f;         // .y of (y, 127): OOB neighbor = 0
}

// ---------------------------------------------------------------------------
// Interval helper: intersect {j : lo < P + Q*j < hi} into [jmn, jmx].
// ---------------------------------------------------------------------------
__device__ __forceinline__ void isect(float P, float Q, float lo, float hi,
                                      float& jmn, float& jmx) {
    if (Q == 0.f) {
        if (P <= lo || P >= hi) { jmn = 1e9f; jmx = -1e9f; }  // empty (boundary => 0 contribution)
    } else {
        float t0 = (lo - P) / Q, t1 = (hi - P) / Q;
        jmn = fmaxf(jmn, fminf(t0, t1));
        jmx = fminf(jmx, fmaxf(t0, t1));
    }
}

// ---------------------------------------------------------------------------
// Kernel 2: radon. warp = (angle a, detector row i), lane = batch b.
// grid (16, 64), block 256 (8 warps -> 8 rows per block).
// ---------------------------------------------------------------------------
__global__ __launch_bounds__(256) void k_radon(const float* __restrict__ angles,
                                               const float* __restrict__ bias,
                                               float* __restrict__ out) {
    const int lane = threadIdx.x & 31;             // batch index
    const int wid  = threadIdx.x >> 5;
    const int i    = blockIdx.x * 8 + wid;         // detector row
    const int a    = blockIdx.y;                   // angle

    const float theta = __ldg(&angles[a]);
    const float c = cosf(theta), s = sinf(theta);
    const float ci = (float)i - 63.5f;

    // xs(j) = ci*c - (j-63.5)*s + 63.5 = A + Bq*j
    // ys(j) = ci*s + (j-63.5)*c + 63.5 = Cq + Dq*j
    const float ax = fmaf(ci, c, 63.5f);
    const float ay = fmaf(ci, s, 63.5f);
    const float A  = fmaf(63.5f, s, ax), Bq = -s;
    const float Cq = fmaf(-63.5f, c, ay), Dq = c;

    // Loose window: any tap possibly nonzero  (xs,ys in (-1,128))
    float jmn = 0.f, jmx = 127.f;
    isect(A, Bq, -1.f, 128.f, jmn, jmx);
    isect(Cq, Dq, -1.f, 128.f, jmn, jmx);
    jmn = fminf(fmaxf(jmn, 0.f), 127.f);
    jmx = fminf(fmaxf(jmx, 0.f), 127.f);
    int jA, jB;
    if (jmn > jmx) { jA = 0; jB = -1; }
    else { jA = max(0, (int)floorf(jmn) - 1); jB = min(127, (int)ceilf(jmx) + 1); }

    // Strict interior window: all 4 taps in-bounds (conservatively shrunk)
    float jmn2 = 0.f, jmx2 = 127.f;
    isect(A, Bq, 0.01f, 126.99f, jmn2, jmx2);
    isect(Cq, Dq, 0.01f, 126.99f, jmn2, jmx2);
    jmn2 = fminf(fmaxf(jmn2, 0.f), 127.f);
    jmx2 = fminf(fmaxf(jmx2, 0.f), 127.f);
    int jC, jD;
    if (jmn2 > jmx2) { jC = jB + 1; jD = jB; }
    else {
        jC = max(jA, (int)ceilf(jmn2) + 1);
        jD = min(jB, (int)floorf(jmx2) - 1);
        if (jC > jD) { jC = jB + 1; jD = jB; }
    }

    const float* Pf = (const float*)g_P;
    float acc0 = 0.f, acc1 = 0.f, acc2 = 0.f, acc3 = 0.f;

    // Exact masked step (reference semantics: clipped indices, zeroed OOB taps)
    auto masked = [&](int j) {
        float cj = (float)j - 63.5f;
        float xs = fmaf(-s, cj, ax);
        float ys = fmaf(c, cj, ay);
        int ix = __float2int_rd(xs), iy = __float2int_rd(ys);
        float wx = xs - (float)ix, wy = ys - (float)iy;
        float u = 1.f - wx, v = 1.f - wy;
        float mx0 = (ix >= 0 && ix < 128) ? 1.f : 0.f;
        float mx1 = (ix >= -1 && ix < 127) ? 1.f : 0.f;
        float my0 = (iy >= 0 && iy < 128) ? 1.f : 0.f;
        float my1 = (iy >= -1 && iy < 127) ? 1.f : 0.f;
        int cx0 = min(max(ix, 0), 127), cx1 = min(max(ix + 1, 0), 127);
        int cy0 = min(max(iy, 0), 127), cy1 = min(max(iy + 1, 0), 127);
        float a0 = u * mx0, a1 = wx * mx1, b0 = v * my0, b1 = wy * my1;
        int r0 = cy0 * 128, r1 = cy1 * 128;
        float v00 = Pf[((r0 + cx0) * 32 + lane) * 2];
        float v01 = Pf[((r0 + cx1) * 32 + lane) * 2];
        float v10 = Pf[((r1 + cx0) * 32 + lane) * 2];
        float v11 = Pf[((r1 + cx1) * 32 + lane) * 2];
        acc0 = fmaf(b0 * a0, v00, acc0);
        acc1 = fmaf(b0 * a1, v01, acc1);
        acc2 = fmaf(b1 * a0, v10, acc2);
        acc3 = fmaf(b1 * a1, v11, acc3);
    };

#pragma unroll 1
    for (int j = jA; j < jC; j++) masked(j);

    // Fast interior: no masks/clamps, paired float2 loads (taps (x,x+1) per row)
#pragma unroll 4
    for (int j = jC; j <= jD; j++) {
        float cj = (float)j - 63.5f;
        float xs = fmaf(-s, cj, ax);
        float ys = fmaf(c, cj, ay);
        int ix = __float2int_rd(xs), iy = __float2int_rd(ys);
        float wx = xs - (float)ix, wy = ys - (float)iy;
        float u = 1.f - wx, v = 1.f - wy;
        int off = (iy * 128 + ix) * 32 + lane;          // float2 index
        float2 p0 = __ldg(&g_P[off]);                   // row iy:   (v00, v01)
        float2 p1 = __ldg(&g_P[off + 4096]);            // row iy+1: (v10, v11)
        acc0 = fmaf(v * u,   p0.x, acc0);
        acc1 = fmaf(v * wx,  p0.y, acc1);
        acc2 = fmaf(wy * u,  p1.x, acc2);
        acc3 = fmaf(wy * wx, p1.y, acc3);
    }

#pragma unroll 1
    for (int j = jD + 1; j <= jB; j++) masked(j);

    float acc = (acc0 + acc1) + (acc2 + acc3) + __ldg(&bias[0]);
    // out[b][0][a][i], b = lane
    out[(lane * NANG + a) * RES + i] = acc;
}

// ---------------------------------------------------------------------------
extern "C" void kernel_launch(void* const* d_in, const int* in_sizes, int n_in,
                              void* d_out, int out_size) {
    const float* x      = (const float*)d_in[0];   // (32,16,128,128) f32
    const float* angles = (const float*)d_in[1];   // (64,)           f32
    const float* conv_w = (const float*)d_in[2];   // (1,16,1,1)      f32
    const float* conv_b = (const float*)d_in[3];   // (1,)            f32
    float* out = (float*)d_out;                    // (32,1,64,128)   f32

    k_weight<<<(BB * RES * RES) / 256, 256>>>(x, conv_w);
    dim3 g(RES / 8, NANG);
    k_radon<<<g, 256>>>(angles, conv_b, out);
}

// round 4
// speedup vs baseline: 1.2202x; 1.2202x over previous
#include <cuda_runtime.h>

// Problem constants
#define BB   32
#define CC   16
#define RES  128
#define NANG 64

// Scratch: weighted image, batch-innermost, x-neighbor-paired.
// g_P[(y*128 + x)*32 + b] = ( W[b][y][x], x<127 ? W[b][y][x+1] : 0 )
// where W[b][y][x] = sum_c conv_w[c] * x[b][c][y][x].
__device__ float2 g_P[RES * RES * BB];

// ---------------------------------------------------------------------------
// Kernel 1: channel-weighted image -> paired (y,x,b) layout.
// One block per image row y. Compute phase reads x coalesced (xi across
// lanes); smem transpose; write phase emits float2 coalesced (b across lanes).
// ---------------------------------------------------------------------------
__global__ __launch_bounds__(1024) void k_weight(const float* __restrict__ x,
                                                 const float* __restrict__ w) {
    __shared__ float S[RES][33];                    // padded: conflict-free both phases
    const int y   = blockIdx.x;
    const int tid = threadIdx.x;

    float wv[CC];
#pragma unroll
    for (int c = 0; c < CC; c++) wv[c] = __ldg(&w[c]);

    // Compute: lanes = consecutive xi -> 128B coalesced reads.
    const int xi = tid & 127;
    const int b0 = tid >> 7;                        // 0..7
#pragma unroll
    for (int k = 0; k < 4; k++) {
        int b = b0 + k * 8;
        const float* px = x + ((size_t)(b * CC) * RES + y) * RES + xi;
        float s = 0.f;
#pragma unroll
        for (int c = 0; c < CC; c++)
            s = fmaf(wv[c], __ldg(&px[(size_t)c * RES * RES]), s);
        S[xi][b] = s;
    }
    __syncthreads();

    // Write: lanes = consecutive b -> consecutive float2 -> 256B coalesced.
    const int b  = tid & 31;
    const int xg = tid >> 5;                        // 0..31
#pragma unroll
    for (int k = 0; k < 4; k++) {
        int x2 = xg + k * 32;
        float2 v;
        v.x = S[x2][b];
        v.y = (x2 < 127) ? S[x2 + 1][b] : 0.f;
        g_P[(y * 128 + x2) * 32 + b] = v;
    }
}

// ---------------------------------------------------------------------------
// Interval helper: intersect {j : lo < P + Q*j < hi} into [jmn, jmx].
// ---------------------------------------------------------------------------
__device__ __forceinline__ void isect(float P, float Q, float lo, float hi,
                                      float& jmn, float& jmx) {
    if (Q == 0.f) {
        if (P <= lo || P >= hi) { jmn = 1e9f; jmx = -1e9f; }
    } else {
        float t0 = (lo - P) / Q, t1 = (hi - P) / Q;
        jmn = fmaxf(jmn, fminf(t0, t1));
        jmx = fminf(jmx, fmaxf(t0, t1));
    }
}

// ---------------------------------------------------------------------------
// Kernel 2: radon. warp = (angle a, detector row i), lane = batch b.
// grid (16, 64), block 256. Row-groups remapped so longest chords run first.
// ---------------------------------------------------------------------------
__global__ __launch_bounds__(256) void k_radon(const float* __restrict__ angles,
                                               const float* __restrict__ bias,
                                               float* __restrict__ out) {
    const int lane = threadIdx.x & 31;              // batch index
    const int wid  = threadIdx.x >> 5;
    // Remap group 0..15 -> 7,8,6,9,5,10,... (center rows first for tail balance)
    const int bx  = blockIdx.x;
    const int grp = (bx & 1) ? (8 + (bx >> 1)) : (7 - (bx >> 1));
    const int i   = grp * 8 + wid;                  // detector row
    const int a   = blockIdx.y;                     // angle

    const float theta = __ldg(&angles[a]);
    const float c = cosf(theta), s = sinf(theta);
    const float ci = (float)i - 63.5f;

    // xs(j) = ax - s*cj,  ys(j) = ay + c*cj,  cj = j - 63.5
    const float ax = fmaf(ci, c, 63.5f);
    const float ay = fmaf(ci, s, 63.5f);
    const float A  = fmaf(63.5f, s, ax), Bq = -s;   // xs as A + Bq*j
    const float Cq = fmaf(-63.5f, c, ay), Dq = c;   // ys as Cq + Dq*j

    // Loose window: any tap possibly nonzero (xs,ys in (-1,128))
    float jmn = 0.f, jmx = 127.f;
    isect(A, Bq, -1.f, 128.f, jmn, jmx);
    isect(Cq, Dq, -1.f, 128.f, jmn, jmx);
    jmn = fminf(fmaxf(jmn, 0.f), 127.f);
    jmx = fminf(fmaxf(jmx, 0.f), 127.f);
    int jA, jB;
    if (jmn > jmx) { jA = 0; jB = -1; }
    else { jA = max(0, (int)floorf(jmn) - 1); jB = min(127, (int)ceilf(jmx) + 1); }

    // Strict interior window: all 4 taps in-bounds (conservatively shrunk)
    float jmn2 = 0.f, jmx2 = 127.f;
    isect(A, Bq, 0.01f, 126.99f, jmn2, jmx2);
    isect(Cq, Dq, 0.01f, 126.99f, jmn2, jmx2);
    jmn2 = fminf(fmaxf(jmn2, 0.f), 127.f);
    jmx2 = fminf(fmaxf(jmx2, 0.f), 127.f);
    int jC, jD;
    if (jmn2 > jmx2) { jC = jB + 1; jD = jB; }
    else {
        jC = max(jA, (int)ceilf(jmn2) + 1);
        jD = min(jB, (int)floorf(jmx2) - 1);
        if (jC > jD) { jC = jB + 1; jD = jB; }
    }

    const float* Pf = (const float*)g_P;
    float acc0 = 0.f, acc1 = 0.f;
    float accm = 0.f;   // masked-path accumulator (kept separate, exact semantics)

    // Exact masked step (reference semantics: clipped indices, zeroed OOB taps)
    auto masked = [&](int j) {
        float cj = (float)j - 63.5f;
        float xs = fmaf(-s, cj, ax);
        float ys = fmaf(c, cj, ay);
        int ix = __float2int_rd(xs), iy = __float2int_rd(ys);
        float wx = xs - (float)ix, wy = ys - (float)iy;
        float u = 1.f - wx, v = 1.f - wy;
        float mx0 = (ix >= 0 && ix < 128) ? 1.f : 0.f;
        float mx1 = (ix >= -1 && ix < 127) ? 1.f : 0.f;
        float my0 = (iy >= 0 && iy < 128) ? 1.f : 0.f;
        float my1 = (iy >= -1 && iy < 127) ? 1.f : 0.f;
        int cx0 = min(max(ix, 0), 127), cx1 = min(max(ix + 1, 0), 127);
        int cy0 = min(max(iy, 0), 127), cy1 = min(max(iy + 1, 0), 127);
        float a0 = u * mx0, a1 = wx * mx1, b0 = v * my0, b1 = wy * my1;
        int r0 = cy0 * 128, r1 = cy1 * 128;
        float v00 = Pf[((r0 + cx0) * 32 + lane) * 2];
        float v01 = Pf[((r0 + cx1) * 32 + lane) * 2];
        float v10 = Pf[((r1 + cx0) * 32 + lane) * 2];
        float v11 = Pf[((r1 + cx1) * 32 + lane) * 2];
        accm = fmaf(b0 * a0, v00, accm);
        accm = fmaf(b0 * a1, v01, accm);
        accm = fmaf(b1 * a0, v10, accm);
        accm = fmaf(b1 * a1, v11, accm);
    };

#pragma unroll 1
    for (int j = jA; j < jC; j++) masked(j);

    // Fast interior: no masks/clamps. ~19 vector instructions / step.
    {
        const float2* base = g_P + lane;
        float cj = (float)jC - 63.5f;               // exact; += 1.0f stays exact
#pragma unroll 4
        for (int j = jC; j <= jD; j++) {
            float xs = fmaf(-s, cj, ax);
            float ys = fmaf(c, cj, ay);
            cj += 1.0f;
            float fx = floorf(xs), fy = floorf(ys);
            float wx = xs - fx,    wy = ys - fy;
            int idx = __float2int_rn(fmaf(fy, 128.f, fx));  // iy*128+ix, exact
            const float2* p = base + (idx << 5);
            float2 p0 = __ldg(p);                    // row iy:   (v00, v01)
            float2 p1 = __ldg(p + 4096);             // row iy+1: (v10, v11)
            float v  = 1.f - wy;
            float s0 = fmaf(wx, p0.y - p0.x, p0.x);  // lerp along x, row iy
            float s1 = fmaf(wx, p1.y - p1.x, p1.x);  // lerp along x, row iy+1
            acc0 = fmaf(v,  s0, acc0);
            acc1 = fmaf(wy, s1, acc1);
        }
    }

#pragma unroll 1
    for (int j = jD + 1; j <= jB; j++) masked(j);

    float acc = (acc0 + acc1) + accm + __ldg(&bias[0]);
    // out[b][0][a][i], b = lane
    out[(lane * NANG + a) * RES + i] = acc;
}

// ---------------------------------------------------------------------------
extern "C" void kernel_launch(void* const* d_in, const int* in_sizes, int n_in,
                              void* d_out, int out_size) {
    const float* x      = (const float*)d_in[0];   // (32,16,128,128) f32
    const float* angles = (const float*)d_in[1];   // (64,)           f32
    const float* conv_w = (const float*)d_in[2];   // (1,16,1,1)      f32
    const float* conv_b = (const float*)d_in[3];   // (1,)            f32
    float* out = (float*)d_out;                    // (32,1,64,128)   f32

    k_weight<<<RES, 1024>>>(x, conv_w);
    dim3 g(RES / 8, NANG);
    k_radon<<<g, 256>>>(angles, conv_b, out);
}

// round 7
// speedup vs baseline: 1.5946x; 1.3068x over previous
#include <cuda_runtime.h>

#define BB   32
#define CC   16
#define RES  128
#define NANG 64

// Weighted image, plain batch-innermost layout: g_W[(y*128+x)*32 + b]
__device__ float g_W[RES * RES * BB];

// ---------------------------------------------------------------------------
// packed f32x2 helpers (sm_103a)
// ---------------------------------------------------------------------------
typedef unsigned long long u64;
__device__ __forceinline__ u64 pk2(float v) {
    u64 r; asm("mov.b64 %0,{%1,%1};" : "=l"(r) : "f"(v)); return r;
}
__device__ __forceinline__ u64 f2fma(u64 a, u64 b, u64 c) {
    u64 d; asm("fma.rn.f32x2 %0,%1,%2,%3;" : "=l"(d) : "l"(a), "l"(b), "l"(c)); return d;
}
__device__ __forceinline__ float2 up2(u64 v) {
    float2 f; asm("mov.b64 {%0,%1},%2;" : "=f"(f.x), "=f"(f.y) : "l"(v)); return f;
}

// ---------------------------------------------------------------------------
// Kernel 1: channel-weighted image -> (y,x,b) layout, coalesced both phases.
// ---------------------------------------------------------------------------
__global__ __launch_bounds__(1024) void k_weight(const float* __restrict__ x,
                                                 const float* __restrict__ w) {
    __shared__ float S[RES][33];
    const int y = blockIdx.x, tid = threadIdx.x;
    float wv[CC];
#pragma unroll
    for (int c = 0; c < CC; c++) wv[c] = __ldg(&w[c]);

    const int xi = tid & 127, b0 = tid >> 7;
#pragma unroll
    for (int k = 0; k < 4; k++) {
        int b = b0 + k * 8;
        const float* px = x + ((size_t)(b * CC) * RES + y) * RES + xi;
        float s = 0.f;
#pragma unroll
        for (int c = 0; c < CC; c++)
            s = fmaf(wv[c], __ldg(&px[(size_t)c * RES * RES]), s);
        S[xi][b] = s;
    }
    __syncthreads();
    const int b = tid & 31, xg = tid >> 5;
#pragma unroll
    for (int k = 0; k < 4; k++) {
        int x2 = xg + k * 32;
        g_W[(y * 128 + x2) * 32 + b] = S[x2][b];
    }
}

// ---------------------------------------------------------------------------
// Interval helper: intersect {j : lo < P + Q*j < hi} into [jmn, jmx].
// ---------------------------------------------------------------------------
__device__ __forceinline__ void isect(float P, float Q, float lo, float hi,
                                      float& jmn, float& jmx) {
    if (Q == 0.f) {
        if (P <= lo || P >= hi) { jmn = 1e9f; jmx = -1e9f; }
    } else {
        float t0 = (lo - P) / Q, t1 = (hi - P) / Q;
        jmn = fmaxf(jmn, fminf(t0, t1));
        jmx = fminf(jmx, fmaxf(t0, t1));
    }
}

__device__ __forceinline__ int wmax(int v) {
#pragma unroll
    for (int o = 16; o; o >>= 1) v = max(v, __shfl_xor_sync(0xffffffffu, v, o));
    return v;
}
__device__ __forceinline__ int wmin(int v) {
#pragma unroll
    for (int o = 16; o; o >>= 1) v = min(v, __shfl_xor_sync(0xffffffffu, v, o));
    return v;
}

// ---------------------------------------------------------------------------
// Kernel 2: radon. Warp covers 4 adjacent rows (lane>>3) x 4 batches/lane
// (q=lane&7, batches 4q..4q+3). 128 samples per warp-step; bilinear in f32x2.
// Block = 64 threads (2 warps, 8 rows), grid (16, 64). Center rows first.
// ---------------------------------------------------------------------------
__global__ __launch_bounds__(64) void k_radon(const float* __restrict__ angles,
                                              const float* __restrict__ bias,
                                              float* __restrict__ out) {
    const int lane = threadIdx.x & 31;
    const int wid  = threadIdx.x >> 5;              // 0..1
    const int sub  = lane >> 3;                     // row within warp 0..3
    const int q    = lane & 7;                      // batch quad: b = 4q..4q+3
    const int bx   = blockIdx.x;
    const int grp  = (bx & 1) ? (8 + (bx >> 1)) : (7 - (bx >> 1));
    const int i    = grp * 8 + wid * 4 + sub;       // detector row
    const int a    = blockIdx.y;                    // angle

    const float theta = __ldg(&angles[a]);
    const float c = cosf(theta), s = sinf(theta);
    const float ci = (float)i - 63.5f;

    // xs(j) = ax - s*cj,  ys(j) = ay + c*cj,  cj = j - 63.5
    const float ax = fmaf(ci, c, 63.5f);
    const float ay = fmaf(ci, s, 63.5f);
    const float A  = fmaf(63.5f, s, ax), Bq = -s;
    const float Cq = fmaf(-63.5f, c, ay), Dq = c;

    // Loose window (any tap possibly nonzero) per row
    float jmn = 0.f, jmx = 127.f;
    isect(A, Bq, -1.f, 128.f, jmn, jmx);
    isect(Cq, Dq, -1.f, 128.f, jmn, jmx);
    jmn = fminf(fmaxf(jmn, 0.f), 127.f);
    jmx = fminf(fmaxf(jmx, 0.f), 127.f);
    int jA, jB;
    if (jmn > jmx) { jA = 0; jB = -1; }
    else { jA = max(0, (int)floorf(jmn) - 1); jB = min(127, (int)ceilf(jmx) + 1); }

    // Strict interior window (all 4 taps in-bounds) per row
    float jmn2 = 0.f, jmx2 = 127.f;
    isect(A, Bq, 0.01f, 126.99f, jmn2, jmx2);
    isect(Cq, Dq, 0.01f, 126.99f, jmn2, jmx2);
    jmn2 = fminf(fmaxf(jmn2, 0.f), 127.f);
    jmx2 = fminf(fmaxf(jmx2, 0.f), 127.f);
    int jC, jD;
    if (jmn2 > jmx2) { jC = jB + 1; jD = jB; }
    else {
        jC = max(jA, (int)ceilf(jmn2) + 1);
        jD = min(jB, (int)floorf(jmx2) - 1);
        if (jC > jD) { jC = jB + 1; jD = jB; }
    }

    // Warp-union windows. Masked path is exact (zero weights) for ANY j,
    // so widening per-lane ranges to the union preserves bit semantics.
    const int jAw = wmin(jA), jBw = wmax(jB);
    const int jCw = wmax(jC);
    int jDw = wmin(jD);
    if (jDw < jCw) jDw = jCw - 1;                   // empty fast region

    // Packed accumulators: A/B = row-iy contribution (batch pairs 01 / 23),
    // C/D = row-iy+1 contribution.
    u64 accA = 0, accB = 0, accC = 0, accD = 0;
    float m0 = 0.f, m1 = 0.f, m2 = 0.f, m3 = 0.f;   // masked-path accumulators

    const float4* W4 = (const float4*)g_W;

    // Exact masked step (reference semantics: clipped indices, zeroed OOB taps)
    auto masked = [&](int j) {
        float cjm = (float)j - 63.5f;
        float xs = fmaf(-s, cjm, ax);
        float ys = fmaf(c, cjm, ay);
        int ix = __float2int_rd(xs), iy = __float2int_rd(ys);
        float wx = xs - (float)ix, wy = ys - (float)iy;
        float u = 1.f - wx, v = 1.f - wy;
        float mx0 = (ix >= 0 && ix < 128) ? 1.f : 0.f;
        float mx1 = (ix >= -1 && ix < 127) ? 1.f : 0.f;
        float my0 = (iy >= 0 && iy < 128) ? 1.f : 0.f;
        float my1 = (iy >= -1 && iy < 127) ? 1.f : 0.f;
        int cx0 = min(max(ix, 0), 127), cx1 = min(max(ix + 1, 0), 127);
        int cy0 = min(max(iy, 0), 127), cy1 = min(max(iy + 1, 0), 127);
        float w00 = (v * my0) * (u * mx0),  w01 = (v * my0) * (wx * mx1);
        float w10 = (wy * my1) * (u * mx0), w11 = (wy * my1) * (wx * mx1);
        float4 v00 = __ldg(&W4[(cy0 * 128 + cx0) * 8 + q]);
        float4 v01 = __ldg(&W4[(cy0 * 128 + cx1) * 8 + q]);
        float4 v10 = __ldg(&W4[(cy1 * 128 + cx0) * 8 + q]);
        float4 v11 = __ldg(&W4[(cy1 * 128 + cx1) * 8 + q]);
        m0 = fmaf(w00, v00.x, fmaf(w01, v01.x, fmaf(w10, v10.x, fmaf(w11, v11.x, m0))));
        m1 = fmaf(w00, v00.y, fmaf(w01, v01.y, fmaf(w10, v10.y, fmaf(w11, v11.y, m1))));
        m2 = fmaf(w00, v00.z, fmaf(w01, v01.z, fmaf(w10, v10.z, fmaf(w11, v11.z, m2))));
        m3 = fmaf(w00, v00.w, fmaf(w01, v01.w, fmaf(w10, v10.w, fmaf(w11, v11.w, m3))));
    };

#pragma unroll 1
    for (int j = jAw; j < jCw; j++) masked(j);

    // Fast interior: no masks/clamps, 4 LDG.128 + 12 packed FMAs per step,
    // 128 samples per warp-step.
    {
        const ulonglong2* Wq = (const ulonglong2*)g_W + q;   // batch-quad base
        const u64 M1 = pk2(-1.f);
        float cj = (float)jCw - 63.5f;               // exact; += 1.0f stays exact
#pragma unroll 2
        for (int j = jCw; j <= jDw; j++) {
            float xs = fmaf(-s, cj, ax);
            float ys = fmaf(c, cj, ay);
            cj += 1.0f;
            float fx = floorf(xs), fy = floorf(ys);
            float wx = xs - fx,    wy = ys - fy;
            int idx = __float2int_rn(fmaf(fy, 128.f, fx));   // iy*128+ix, exact
            const ulonglong2* p = Wq + ((long)idx << 3);
            ulonglong2 t00 = __ldg(p);                       // (iy  ,ix  ) batches 4q..4q+3
            ulonglong2 t01 = __ldg(p + 8);                   // (iy  ,ix+1)
            ulonglong2 t10 = __ldg(p + 1024);                // (iy+1,ix  )
            ulonglong2 t11 = __ldg(p + 1032);                // (iy+1,ix+1)
            u64 wx2 = pk2(wx), wy2 = pk2(wy), v2 = pk2(1.f - wy);
            // lerp along x:  s = v0 + wx*(v1 - v0)   (v1-v0 via fma with -1)
            u64 s0a = f2fma(wx2, f2fma(t00.x, M1, t01.x), t00.x);
            u64 s0b = f2fma(wx2, f2fma(t00.y, M1, t01.y), t00.y);
            u64 s1a = f2fma(wx2, f2fma(t10.x, M1, t11.x), t10.x);
            u64 s1b = f2fma(wx2, f2fma(t10.y, M1, t11.y), t10.y);
            accA = f2fma(v2,  s0a, accA);
            accB = f2fma(v2,  s0b, accB);
            accC = f2fma(wy2, s1a, accC);
            accD = f2fma(wy2, s1b, accD);
        }
    }

#pragma unroll 1
    for (int j = jDw + 1; j <= jBw; j++) masked(j);

    // Combine & store: b = 4q + k, out[b][0][a][i]
    float2 Af = up2(accA), Bf = up2(accB), Cf = up2(accC), Df = up2(accD);
    const float bv = __ldg(&bias[0]);
    float r0 = (Af.x + Cf.x) + m0 + bv;
    float r1 = (Af.y + Cf.y) + m1 + bv;
    float r2 = (Bf.x + Df.x) + m2 + bv;
    float r3 = (Bf.y + Df.y) + m3 + bv;
    const int b0 = 4 * q;
    out[((b0 + 0) * NANG + a) * RES + i] = r0;
    out[((b0 + 1) * NANG + a) * RES + i] = r1;
    out[((b0 + 2) * NANG + a) * RES + i] = r2;
    out[((b0 + 3) * NANG + a) * RES + i] = r3;
}

// ---------------------------------------------------------------------------
extern "C" void kernel_launch(void* const* d_in, const int* in_sizes, int n_in,
                              void* d_out, int out_size) {
    const float* x      = (const float*)d_in[0];   // (32,16,128,128) f32
    const float* angles = (const float*)d_in[1];   // (64,)           f32
    const float* conv_w = (const float*)d_in[2];   // (1,16,1,1)      f32
    const float* conv_b = (const float*)d_in[3];   // (1,)            f32
    float* out = (float*)d_out;                    // (32,1,64,128)   f32

    k_weight<<<RES, 1024>>>(x, conv_w);
    dim3 g(16, NANG);
    k_radon<<<g, 64>>>(angles, conv_b, out);
}

// round 8
// speedup vs baseline: 1.8569x; 1.1645x over previous
#include <cuda_runtime.h>

#define BB   32
#define CC   16
#define RES  128
#define NANG 64

// Weighted image, plain batch-innermost layout: g_W[(y*128+x)*32 + b]
__device__ float g_W[RES * RES * BB];

// ---------------------------------------------------------------------------
// packed f32x2 helpers (sm_103a)
// ---------------------------------------------------------------------------
typedef unsigned long long u64;
__device__ __forceinline__ u64 pk2(float v) {
    u64 r; asm("mov.b64 %0,{%1,%1};" : "=l"(r) : "f"(v)); return r;
}
__device__ __forceinline__ u64 f2fma(u64 a, u64 b, u64 c) {
    u64 d; asm("fma.rn.f32x2 %0,%1,%2,%3;" : "=l"(d) : "l"(a), "l"(b), "l"(c)); return d;
}
__device__ __forceinline__ float2 up2(u64 v) {
    float2 f; asm("mov.b64 {%0,%1},%2;" : "=f"(f.x), "=f"(f.y) : "l"(v)); return f;
}

// ---------------------------------------------------------------------------
// Kernel 1: channel-weighted image -> (y,x,b) layout, coalesced both phases.
// ---------------------------------------------------------------------------
__global__ __launch_bounds__(1024) void k_weight(const float* __restrict__ x,
                                                 const float* __restrict__ w) {
    __shared__ float S[RES][33];
    const int y = blockIdx.x, tid = threadIdx.x;
    float wv[CC];
#pragma unroll
    for (int c = 0; c < CC; c++) wv[c] = __ldg(&w[c]);

    const int xi = tid & 127, b0 = tid >> 7;
#pragma unroll
    for (int k = 0; k < 4; k++) {
        int b = b0 + k * 8;
        const float* px = x + ((size_t)(b * CC) * RES + y) * RES + xi;
        float s = 0.f;
#pragma unroll
        for (int c = 0; c < CC; c++)
            s = fmaf(wv[c], __ldg(&px[(size_t)c * RES * RES]), s);
        S[xi][b] = s;
    }
    __syncthreads();
    const int b = tid & 31, xg = tid >> 5;
#pragma unroll
    for (int k = 0; k < 4; k++) {
        int x2 = xg + k * 32;
        g_W[(y * 128 + x2) * 32 + b] = S[x2][b];
    }
}

// ---------------------------------------------------------------------------
// Interval helper: intersect {j : lo < P + Q*j < hi} into [jmn, jmx].
// ---------------------------------------------------------------------------
__device__ __forceinline__ void isect(float P, float Q, float lo, float hi,
                                      float& jmn, float& jmx) {
    if (Q == 0.f) {
        if (P <= lo || P >= hi) { jmn = 1e9f; jmx = -1e9f; }
    } else {
        float t0 = (lo - P) / Q, t1 = (hi - P) / Q;
        jmn = fmaxf(jmn, fminf(t0, t1));
        jmx = fminf(jmx, fmaxf(t0, t1));
    }
}

__device__ __forceinline__ int wmax(int v) {
#pragma unroll
    for (int o = 16; o; o >>= 1) v = max(v, __shfl_xor_sync(0xffffffffu, v, o));
    return v;
}
__device__ __forceinline__ int wmin(int v) {
#pragma unroll
    for (int o = 16; o; o >>= 1) v = min(v, __shfl_xor_sync(0xffffffffu, v, o));
    return v;
}

// ---------------------------------------------------------------------------
// Kernel 2: radon. Block = 256 threads = 8 warps = 2 row-quads x 4 j-segments.
// Warp lanes: sub = lane>>3 (row in quad), q = lane&7 (batch quad 4q..4q+3).
// Each warp sums its segment of the ray; segments reduced in smem in fixed
// order (deterministic). grid (16, 64); center row-groups scheduled first.
// ---------------------------------------------------------------------------
__global__ __launch_bounds__(256) void k_radon(const float* __restrict__ angles,
                                               const float* __restrict__ bias,
                                               float* __restrict__ out) {
    __shared__ float4 red[8][32];

    const int tid  = threadIdx.x;
    const int lane = tid & 31;
    const int w    = tid >> 5;                      // 0..7
    const int quad = w & 1;                         // row-quad within group
    const int seg  = w >> 1;                        // j-segment 0..3
    const int sub  = lane >> 3;                     // row within quad
    const int q    = lane & 7;                      // batch quad: b = 4q..4q+3
    const int bx   = blockIdx.x;
    const int grp  = (bx & 1) ? (8 + (bx >> 1)) : (7 - (bx >> 1));
    const int i    = grp * 8 + quad * 4 + sub;      // detector row
    const int a    = blockIdx.y;                    // angle

    const float theta = __ldg(&angles[a]);
    const float c = cosf(theta), s = sinf(theta);
    const float ci = (float)i - 63.5f;

    // xs(j) = ax - s*cj,  ys(j) = ay + c*cj,  cj = j - 63.5
    const float ax = fmaf(ci, c, 63.5f);
    const float ay = fmaf(ci, s, 63.5f);
    const float A  = fmaf(63.5f, s, ax), Bq = -s;
    const float Cq = fmaf(-63.5f, c, ay), Dq = c;

    // Loose window (any tap possibly nonzero) per row
    float jmn = 0.f, jmx = 127.f;
    isect(A, Bq, -1.f, 128.f, jmn, jmx);
    isect(Cq, Dq, -1.f, 128.f, jmn, jmx);
    jmn = fminf(fmaxf(jmn, 0.f), 127.f);
    jmx = fminf(fmaxf(jmx, 0.f), 127.f);
    int jA, jB;
    if (jmn > jmx) { jA = 0; jB = -1; }
    else { jA = max(0, (int)floorf(jmn) - 1); jB = min(127, (int)ceilf(jmx) + 1); }

    // Strict interior window (all 4 taps in-bounds) per row
    float jmn2 = 0.f, jmx2 = 127.f;
    isect(A, Bq, 0.01f, 126.99f, jmn2, jmx2);
    isect(Cq, Dq, 0.01f, 126.99f, jmn2, jmx2);
    jmn2 = fminf(fmaxf(jmn2, 0.f), 127.f);
    jmx2 = fminf(fmaxf(jmx2, 0.f), 127.f);
    int jC, jD;
    if (jmn2 > jmx2) { jC = jB + 1; jD = jB; }
    else {
        jC = max(jA, (int)ceilf(jmn2) + 1);
        jD = min(jB, (int)floorf(jmx2) - 1);
        if (jC > jD) { jC = jB + 1; jD = jB; }
    }

    // Warp-union windows over the 4 rows of this quad. Masked path is exact
    // (zero weights) for ANY j, so widening to the union preserves semantics.
    const int jAw = wmin(jA), jBw = wmax(jB);
    const int jCw = wmax(jC);
    int jDw = wmin(jD);
    if (jDw < jCw - 1) jDw = jCw - 1;               // keep jCw <= jDw+1

    // This warp's segment of the union window [jAw, jBw]
    const int len   = jBw - jAw + 1;                // may be <= 0 (empty)
    const int segLo = jAw + (seg * len) / 4;
    const int segHi = jAw + ((seg + 1) * len) / 4 - 1;

    // Packed accumulators: A/B = row-iy contribution (batch pairs 01 / 23),
    // C/D = row-iy+1 contribution.
    u64 accA = 0, accB = 0, accC = 0, accD = 0;
    float m0 = 0.f, m1 = 0.f, m2 = 0.f, m3 = 0.f;   // masked-path accumulators

    const float4* W4 = (const float4*)g_W;

    // Exact masked step (reference semantics: clipped indices, zeroed OOB taps)
    auto masked = [&](int j) {
        float cjm = (float)j - 63.5f;
        float xs = fmaf(-s, cjm, ax);
        float ys = fmaf(c, cjm, ay);
        int ix = __float2int_rd(xs), iy = __float2int_rd(ys);
        float wx = xs - (float)ix, wy = ys - (float)iy;
        float u = 1.f - wx, v = 1.f - wy;
        float mx0 = (ix >= 0 && ix < 128) ? 1.f : 0.f;
        float mx1 = (ix >= -1 && ix < 127) ? 1.f : 0.f;
        float my0 = (iy >= 0 && iy < 128) ? 1.f : 0.f;
        float my1 = (iy >= -1 && iy < 127) ? 1.f : 0.f;
        int cx0 = min(max(ix, 0), 127), cx1 = min(max(ix + 1, 0), 127);
        int cy0 = min(max(iy, 0), 127), cy1 = min(max(iy + 1, 0), 127);
        float w00 = (v * my0) * (u * mx0),  w01 = (v * my0) * (wx * mx1);
        float w10 = (wy * my1) * (u * mx0), w11 = (wy * my1) * (wx * mx1);
        float4 v00 = __ldg(&W4[(cy0 * 128 + cx0) * 8 + q]);
        float4 v01 = __ldg(&W4[(cy0 * 128 + cx1) * 8 + q]);
        float4 v10 = __ldg(&W4[(cy1 * 128 + cx0) * 8 + q]);
        float4 v11 = __ldg(&W4[(cy1 * 128 + cx1) * 8 + q]);
        m0 = fmaf(w00, v00.x, fmaf(w01, v01.x, fmaf(w10, v10.x, fmaf(w11, v11.x, m0))));
        m1 = fmaf(w00, v00.y, fmaf(w01, v01.y, fmaf(w10, v10.y, fmaf(w11, v11.y, m1))));
        m2 = fmaf(w00, v00.z, fmaf(w01, v01.z, fmaf(w10, v10.z, fmaf(w11, v11.z, m2))));
        m3 = fmaf(w00, v00.w, fmaf(w01, v01.w, fmaf(w10, v10.w, fmaf(w11, v11.w, m3))));
    };

    // Segment partition: head (masked, j<jCw) | fast [jCw,jDw] | tail (j>jDw)
    const int h1 = min(segHi, jCw - 1);
#pragma unroll 1
    for (int j = segLo; j <= h1; j++) masked(j);

    const int f0 = max(segLo, jCw), f1 = min(segHi, jDw);
    if (f0 <= f1) {
        const ulonglong2* Wq = (const ulonglong2*)g_W + q;   // batch-quad base
        const u64 M1 = pk2(-1.f);
        float cj = (float)f0 - 63.5f;                // exact; += 1.0f stays exact
#pragma unroll 4
        for (int j = f0; j <= f1; j++) {
            float xs = fmaf(-s, cj, ax);
            float ys = fmaf(c, cj, ay);
            cj += 1.0f;
            float fx = floorf(xs), fy = floorf(ys);
            float wx = xs - fx,    wy = ys - fy;
            int idx = __float2int_rn(fmaf(fy, 128.f, fx));   // iy*128+ix, exact
            const ulonglong2* p = Wq + ((long)idx << 3);
            ulonglong2 t00 = __ldg(p);                       // (iy  ,ix  )
            ulonglong2 t01 = __ldg(p + 8);                   // (iy  ,ix+1)
            ulonglong2 t10 = __ldg(p + 1024);                // (iy+1,ix  )
            ulonglong2 t11 = __ldg(p + 1032);                // (iy+1,ix+1)
            u64 wx2 = pk2(wx), wy2 = pk2(wy), v2 = pk2(1.f - wy);
            u64 s0a = f2fma(wx2, f2fma(t00.x, M1, t01.x), t00.x);
            u64 s0b = f2fma(wx2, f2fma(t00.y, M1, t01.y), t00.y);
            u64 s1a = f2fma(wx2, f2fma(t10.x, M1, t11.x), t10.x);
            u64 s1b = f2fma(wx2, f2fma(t10.y, M1, t11.y), t10.y);
            accA = f2fma(v2,  s0a, accA);
            accB = f2fma(v2,  s0b, accB);
            accC = f2fma(wy2, s1a, accC);
            accD = f2fma(wy2, s1b, accD);
        }
    }

    const int t0 = max(segLo, jDw + 1);
#pragma unroll 1
    for (int j = t0; j <= segHi; j++) masked(j);

    // Per-warp partial results -> smem
    float2 Af = up2(accA), Bf = up2(accB), Cf = up2(accC), Df = up2(accD);
    float4 part;
    part.x = (Af.x + Cf.x) + m0;
    part.y = (Af.y + Cf.y) + m1;
    part.z = (Bf.x + Df.x) + m2;
    part.w = (Bf.y + Df.y) + m3;
    red[w][lane] = part;
    __syncthreads();

    // Reduce 4 segments in fixed order (deterministic) and store.
    if (tid < 64) {
        const int rq = tid >> 5, ln = tid & 31;
        const int qq = ln & 7, sb = ln >> 3;
        float4 r = red[rq][ln];                      // seg 0
#pragma unroll
        for (int ss = 1; ss < 4; ss++) {
            float4 p = red[ss * 2 + rq][ln];
            r.x += p.x; r.y += p.y; r.z += p.z; r.w += p.w;
        }
        const float bv = __ldg(&bias[0]);
        const int ii = grp * 8 + rq * 4 + sb;
        const int b0 = 4 * qq;
        out[((b0 + 0) * NANG + a) * RES + ii] = r.x + bv;
        out[((b0 + 1) * NANG + a) * RES + ii] = r.y + bv;
        out[((b0 + 2) * NANG + a) * RES + ii] = r.z + bv;
        out[((b0 + 3) * NANG + a) * RES + ii] = r.w + bv;
    }
}

// ---------------------------------------------------------------------------
extern "C" void kernel_launch(void* const* d_in, const int* in_sizes, int n_in,
                              void* d_out, int out_size) {
    const float* x      = (const float*)d_in[0];   // (32,16,128,128) f32
    const float* angles = (const float*)d_in[1];   // (64,)           f32
    const float* conv_w = (const float*)d_in[2];   // (1,16,1,1)      f32
    const float* conv_b = (const float*)d_in[3];   // (1,)            f32
    float* out = (float*)d_out;                    // (32,1,64,128)   f32

    k_weight<<<RES, 1024>>>(x, conv_w);
    dim3 g(16, NANG);
    k_radon<<<g, 256>>>(angles, conv_b, out);
}